// round 1
// baseline (speedup 1.0000x reference)
#include <cuda_runtime.h>
#include <math.h>

#define N_NODES 65536
#define DEG     16
#define D       64
#define D2      128
#define BQ      1024
#define NEGQ    10
#define NQ      (BQ + BQ + NEGQ)     /* 2058 */
#define MAXLIST (NQ * DEG)           /* 32928 */
#define NPB     64                   /* nodes per block in h1 kernel */

__device__ int   d_flags[N_NODES];
__device__ int   d_list[MAXLIST];
__device__ int   d_cnt;
__device__ float d_h1[N_NODES * D];

// ---------------------------------------------------------------------------
// 1) zero flags + counter (must rerun every graph replay)
// ---------------------------------------------------------------------------
__global__ void k_zero() {
    int i = blockIdx.x * blockDim.x + threadIdx.x;
    if (i < N_NODES) d_flags[i] = 0;
    if (i == 0) d_cnt = 0;
}

// ---------------------------------------------------------------------------
// 2) build deduplicated list of nodes whose h1 is needed
//    (the 16 neighbors of each of the 2058 query nodes)
// ---------------------------------------------------------------------------
__global__ void k_build(const int* __restrict__ adj,
                        const int* __restrict__ in1,
                        const int* __restrict__ in2,
                        const int* __restrict__ neg) {
    int t = blockIdx.x * blockDim.x + threadIdx.x;
    if (t >= NQ * DEG) return;
    int q = t / DEG, k = t % DEG;
    int node = (q < BQ) ? in1[q] : (q < 2 * BQ) ? in2[q - BQ] : neg[q - 2 * BQ];
    int m = adj[node * DEG + k];
    if (atomicExch(&d_flags[m], 1) == 0) {
        int p = atomicAdd(&d_cnt, 1);
        d_list[p] = m;
    }
}

// ---------------------------------------------------------------------------
// 3) h1[n] = tanh( [feat[n], sum_k feat[adj[n][k]]] @ W1.T + b1 )
//    only for listed nodes. blockDim=256 -> 4 groups of 64 threads,
//    each group processes 4 nodes at once (x packed node-minor as float4).
// ---------------------------------------------------------------------------
__global__ __launch_bounds__(256) void k_h1(const float* __restrict__ feat,
                                            const int*   __restrict__ adj,
                                            const float* __restrict__ W1,
                                            const float* __restrict__ b1) {
    __shared__ float W1t[2 * D][D];     // [i][j] = W1[j][i]   (32 KB)
    __shared__ float b1s[D];
    __shared__ float xq[4][2 * D][4];   // [group][i][node-sub] (8 KB)

    int cnt  = d_cnt;
    int base = blockIdx.x * NPB;
    if (base >= cnt) return;

    int tid = threadIdx.x;
    for (int idx = tid; idx < 2 * D * D; idx += 256) {
        int i = idx >> 6, j = idx & 63;
        W1t[i][j] = W1[j * (2 * D) + i];
    }
    if (tid < D) b1s[tid] = b1[tid];

    int g = tid >> 6;      // group 0..3
    int j = tid & 63;      // output column
    __syncthreads();

    for (int it = 0; it < NPB / 16; ++it) {
        int qbase = base + it * 16 + g * 4;   // this group's 4 nodes
        int nn[4];
        #pragma unroll
        for (int s = 0; s < 4; ++s) {
            int li = qbase + s;
            int n  = (li < cnt) ? d_list[li] : -1;
            nn[s]  = n;
            float self = 0.f, sum = 0.f;
            if (n >= 0) {
                self = feat[n * D + j];
                const int* a = adj + n * DEG;
                #pragma unroll
                for (int k = 0; k < DEG; ++k)
                    sum += feat[a[k] * D + j];
            }
            xq[g][j][s]     = self;
            xq[g][D + j][s] = sum;
        }
        __syncthreads();

        float acc0 = b1s[j], acc1 = b1s[j], acc2 = b1s[j], acc3 = b1s[j];
        #pragma unroll 8
        for (int i = 0; i < 2 * D; ++i) {
            float  w  = W1t[i][j];
            float4 xv = *(const float4*)&xq[g][i][0];  // broadcast within warp
            acc0 += w * xv.x; acc1 += w * xv.y;
            acc2 += w * xv.z; acc3 += w * xv.w;
        }
        if (nn[0] >= 0) d_h1[nn[0] * D + j] = tanhf(acc0);
        if (nn[1] >= 0) d_h1[nn[1] * D + j] = tanhf(acc1);
        if (nn[2] >= 0) d_h1[nn[2] * D + j] = tanhf(acc2);
        if (nn[3] >= 0) d_h1[nn[3] * D + j] = tanhf(acc3);
        __syncthreads();
    }
}

// ---------------------------------------------------------------------------
// 4) out[q] = normalize( [feat[node], sum_k h1[adj[node][k]]] @ W2.T + b2 )
//    one query per block iteration, 128 threads = 128 output columns.
//    W2 rows live in L1 across the ~4 queries each block handles.
// ---------------------------------------------------------------------------
__global__ __launch_bounds__(128) void k_hop2(const float* __restrict__ feat,
                                              const int*   __restrict__ adj,
                                              const int*   __restrict__ in1,
                                              const int*   __restrict__ in2,
                                              const int*   __restrict__ neg,
                                              const float* __restrict__ W2,
                                              const float* __restrict__ b2,
                                              float*       __restrict__ out) {
    __shared__ float x[2 * D];
    __shared__ float red[4];
    int tid = threadIdx.x;

    for (int q = blockIdx.x; q < NQ; q += gridDim.x) {
        int node = (q < BQ) ? in1[q] : (q < 2 * BQ) ? in2[q - BQ] : neg[q - 2 * BQ];
        if (tid < D) {
            x[tid] = feat[node * D + tid];
        } else {
            int jj = tid - D;
            const int* a = adj + node * DEG;
            float s = 0.f;
            #pragma unroll
            for (int k = 0; k < DEG; ++k)
                s += d_h1[a[k] * D + jj];
            x[D + jj] = s;
        }
        __syncthreads();

        float acc = b2[tid];
        const float4* wrow = (const float4*)(W2 + tid * (2 * D));
        #pragma unroll 8
        for (int i4 = 0; i4 < (2 * D) / 4; ++i4) {
            float4 w = wrow[i4];
            acc += w.x * x[i4 * 4 + 0] + w.y * x[i4 * 4 + 1]
                 + w.z * x[i4 * 4 + 2] + w.w * x[i4 * 4 + 3];
        }

        float sq = acc * acc;
        #pragma unroll
        for (int off = 16; off; off >>= 1)
            sq += __shfl_xor_sync(0xffffffffu, sq, off);
        if ((tid & 31) == 0) red[tid >> 5] = sq;
        __syncthreads();

        float tot = red[0] + red[1] + red[2] + red[3];
        float nrm = fmaxf(sqrtf(tot), 1e-12f);
        out[q * D2 + tid] = acc / nrm;
        __syncthreads();   // protect x/red before next iteration
    }
}

// ---------------------------------------------------------------------------
extern "C" void kernel_launch(void* const* d_in, const int* in_sizes, int n_in,
                              void* d_out, int out_size) {
    const float* feat = (const float*)d_in[0];   // [N, 64]
    const int*   adj  = (const int*)  d_in[1];   // [N, 16]
    const int*   in1  = (const int*)  d_in[2];   // [1024]
    const int*   in2  = (const int*)  d_in[3];   // [1024]
    const int*   neg  = (const int*)  d_in[4];   // [10]
    const float* W1   = (const float*)d_in[5];   // [64, 128]
    const float* b1   = (const float*)d_in[6];   // [64]
    const float* W2   = (const float*)d_in[7];   // [128, 128]
    const float* b2   = (const float*)d_in[8];   // [128]
    float*       out  = (float*)d_out;           // [2058, 128]

    k_zero<<<(N_NODES + 255) / 256, 256>>>();
    k_build<<<(NQ * DEG + 255) / 256, 256>>>(adj, in1, in2, neg);
    k_h1<<<(MAXLIST + NPB - 1) / NPB, 256>>>(feat, adj, W1, b1);
    k_hop2<<<512, 128>>>(feat, adj, in1, in2, neg, W2, b2, out);
}

// round 2
// speedup vs baseline: 1.0025x; 1.0025x over previous
#include <cuda_runtime.h>
#include <math.h>

#define N_NODES 65536
#define DEG     16
#define D       64
#define D2      128
#define BQ      1024
#define NEGQ    10
#define NQ      (BQ + BQ + NEGQ)     /* 2058 */
#define MAXLIST (NQ * DEG)           /* 32928 */
#define QPB     8                    /* queries per block in hop2 */

__device__ int   d_flags[N_NODES + 1];   // [N_NODES] doubles as the list counter
__device__ int   d_list[MAXLIST];
__device__ float d_h1[N_NODES * D];

// ---------------------------------------------------------------------------
// 1) zero flags + counter
// ---------------------------------------------------------------------------
__global__ void k_zero() {
    int i = blockIdx.x * blockDim.x + threadIdx.x;
    int4* p = (int4*)d_flags;
    if (i < N_NODES / 4) p[i] = make_int4(0, 0, 0, 0);
    if (i == 0) d_flags[N_NODES] = 0;
}

// ---------------------------------------------------------------------------
// 2) dedup list of nodes needing h1
// ---------------------------------------------------------------------------
__global__ void k_build(const int* __restrict__ adj,
                        const int* __restrict__ in1,
                        const int* __restrict__ in2,
                        const int* __restrict__ neg) {
    int t = blockIdx.x * blockDim.x + threadIdx.x;
    if (t >= NQ * DEG) return;
    int q = t / DEG, k = t % DEG;
    int node = (q < BQ) ? in1[q] : (q < 2 * BQ) ? in2[q - BQ] : neg[q - 2 * BQ];
    int m = adj[node * DEG + k];
    if (atomicExch(&d_flags[m], 1) == 0) {
        int p = atomicAdd(&d_flags[N_NODES], 1);
        d_list[p] = m;
    }
}

// ---------------------------------------------------------------------------
// 3) h1 for listed nodes. One 16-node tile per block, 256 threads =
//    4 groups x 64 cols, 4 nodes per group (node-minor float4 packing).
//    smem 40.25KB -> 5 resident blocks/SM for gather/GEMV overlap.
// ---------------------------------------------------------------------------
__global__ __launch_bounds__(256) void k_h1(const float* __restrict__ feat,
                                            const int*   __restrict__ adj,
                                            const float* __restrict__ W1,
                                            const float* __restrict__ b1) {
    __shared__ float W1t[2 * D][D];     // [i][j] = W1[j][i]   (32 KB)
    __shared__ float b1s[D];
    __shared__ float xq[4][2 * D][4];   // [group][i][node-sub] (8 KB)

    int cnt  = d_flags[N_NODES];
    int base = blockIdx.x * 16;
    if (base >= cnt) return;

    int tid = threadIdx.x;
    #pragma unroll
    for (int r = 0; r < 32; ++r) {
        int idx = r * 256 + tid;
        int i = idx >> 6, j = idx & 63;
        W1t[i][j] = W1[j * (2 * D) + i];
    }
    if (tid < D) b1s[tid] = b1[tid];

    int g = tid >> 6;      // group 0..3
    int j = tid & 63;      // output column
    int qbase = base + g * 4;

    int nn[4];
    #pragma unroll
    for (int s = 0; s < 4; ++s) {
        int li = qbase + s;
        int n  = (li < cnt) ? d_list[li] : -1;
        nn[s]  = n;
        float self = 0.f, sum = 0.f;
        if (n >= 0) {
            self = feat[n * D + j];
            const int* a = adj + n * DEG;
            #pragma unroll
            for (int k = 0; k < DEG; ++k)
                sum += feat[a[k] * D + j];
        }
        xq[g][j][s]     = self;
        xq[g][D + j][s] = sum;
    }
    __syncthreads();

    float a0 = b1s[j], a1 = a0, a2 = a0, a3 = a0;
    #pragma unroll 16
    for (int i = 0; i < 2 * D; ++i) {
        float  w  = W1t[i][j];
        float4 xv = *(const float4*)&xq[g][i][0];  // warp broadcast
        a0 += w * xv.x; a1 += w * xv.y;
        a2 += w * xv.z; a3 += w * xv.w;
    }
    if (nn[0] >= 0) d_h1[nn[0] * D + j] = tanhf(a0);
    if (nn[1] >= 0) d_h1[nn[1] * D + j] = tanhf(a1);
    if (nn[2] >= 0) d_h1[nn[2] * D + j] = tanhf(a2);
    if (nn[3] >= 0) d_h1[nn[3] * D + j] = tanhf(a3);
}

// ---------------------------------------------------------------------------
// 4) hop-2 + normalize, 8 queries per block of 128 threads.
//    Each thread streams its own W2 row (L1-hot) ONCE per 8 queries.
// ---------------------------------------------------------------------------
__global__ __launch_bounds__(128) void k_hop2(const float* __restrict__ feat,
                                              const int*   __restrict__ adj,
                                              const int*   __restrict__ in1,
                                              const int*   __restrict__ in2,
                                              const int*   __restrict__ neg,
                                              const float* __restrict__ W2,
                                              const float* __restrict__ b2,
                                              float*       __restrict__ out) {
    __shared__ float x[2 * D][QPB];     // concat inputs, query-minor (4 KB)
    __shared__ float ys[QPB][D2 + 1];   // outputs for norm reduction
    __shared__ float inv[QPB];

    int tid = threadIdx.x;
    int qb  = blockIdx.x * QPB;

    int nodes[QPB];
    #pragma unroll
    for (int s = 0; s < QPB; ++s) {
        int q = qb + s;
        nodes[s] = (q >= NQ) ? -1
                 : (q < BQ) ? in1[q]
                 : (q < 2 * BQ) ? in2[q - BQ]
                 : neg[q - 2 * BQ];
    }

    if (tid < D) {                       // self features for all 8 queries
        int j = tid;
        #pragma unroll
        for (int s = 0; s < QPB; ++s)
            x[j][s] = (nodes[s] >= 0) ? feat[nodes[s] * D + j] : 0.f;
    } else {                             // neighbor h1 sums
        int j = tid - D;
        #pragma unroll
        for (int s = 0; s < QPB; ++s) {
            float sum = 0.f;
            if (nodes[s] >= 0) {
                const int* a = adj + nodes[s] * DEG;
                #pragma unroll
                for (int k = 0; k < DEG; ++k)
                    sum += d_h1[a[k] * D + j];
            }
            x[D + j][s] = sum;
        }
    }
    __syncthreads();

    float acc[QPB];
    float bb = b2[tid];
    #pragma unroll
    for (int s = 0; s < QPB; ++s) acc[s] = bb;

    const float4* wrow = (const float4*)(W2 + tid * (2 * D));
    #pragma unroll 8
    for (int i4 = 0; i4 < (2 * D) / 4; ++i4) {
        float4 w = wrow[i4];
        #pragma unroll
        for (int e = 0; e < 4; ++e) {
            float we = (e == 0) ? w.x : (e == 1) ? w.y : (e == 2) ? w.z : w.w;
            int   i  = i4 * 4 + e;
            float4 lo = *(const float4*)&x[i][0];   // warp broadcast
            float4 hi = *(const float4*)&x[i][4];
            acc[0] += we * lo.x; acc[1] += we * lo.y;
            acc[2] += we * lo.z; acc[3] += we * lo.w;
            acc[4] += we * hi.x; acc[5] += we * hi.y;
            acc[6] += we * hi.z; acc[7] += we * hi.w;
        }
    }

    #pragma unroll
    for (int s = 0; s < QPB; ++s) ys[s][tid] = acc[s];
    __syncthreads();

    int w = tid >> 5, l = tid & 31;      // warp w handles rows 2w, 2w+1
    #pragma unroll
    for (int r = 0; r < 2; ++r) {
        int s = 2 * w + r;
        float v = ys[s][l]      * ys[s][l];
        v      += ys[s][l + 32] * ys[s][l + 32];
        v      += ys[s][l + 64] * ys[s][l + 64];
        v      += ys[s][l + 96] * ys[s][l + 96];
        #pragma unroll
        for (int off = 16; off; off >>= 1)
            v += __shfl_xor_sync(0xffffffffu, v, off);
        if (l == 0) inv[s] = 1.0f / fmaxf(sqrtf(v), 1e-12f);
    }
    __syncthreads();

    #pragma unroll
    for (int s = 0; s < QPB; ++s)
        if (nodes[s] >= 0)
            out[(qb + s) * D2 + tid] = acc[s] * inv[s];
}

// ---------------------------------------------------------------------------
extern "C" void kernel_launch(void* const* d_in, const int* in_sizes, int n_in,
                              void* d_out, int out_size) {
    const float* feat = (const float*)d_in[0];   // [N, 64]
    const int*   adj  = (const int*)  d_in[1];   // [N, 16]
    const int*   in1  = (const int*)  d_in[2];   // [1024]
    const int*   in2  = (const int*)  d_in[3];   // [1024]
    const int*   neg  = (const int*)  d_in[4];   // [10]
    const float* W1   = (const float*)d_in[5];   // [64, 128]
    const float* b1   = (const float*)d_in[6];   // [64]
    const float* W2   = (const float*)d_in[7];   // [128, 128]
    const float* b2   = (const float*)d_in[8];   // [128]
    float*       out  = (float*)d_out;           // [2058, 128]

    k_zero<<<(N_NODES / 4 + 255) / 256, 256>>>();
    k_build<<<(NQ * DEG + 255) / 256, 256>>>(adj, in1, in2, neg);
    k_h1<<<(MAXLIST + 15) / 16, 256>>>(feat, adj, W1, b1);
    k_hop2<<<(NQ + QPB - 1) / QPB, 128>>>(feat, adj, in1, in2, neg, W2, b2, out);
}

// round 3
// speedup vs baseline: 1.8269x; 1.8223x over previous
#include <cuda_runtime.h>
#include <math.h>

#define N_NODES 65536
#define DEG     16
#define D       64
#define D2      128
#define BQ      1024
#define NEGQ    10
#define NQ      (BQ + BQ + NEGQ)     /* 2058 queries */
#define NSLOT   (NQ * DEG)           /* 32928 h1 slots */
#define WPAD    132                  /* padded W1 row: conflict-free, 16B-aligned */
#define GRID_H1 740                  /* 5 blocks/SM * 148 SMs */

__device__ float d_h1s[NSLOT * D];   // 8.4 MB dense scratch, slot-major

__device__ __forceinline__ int qnode_of(int q,
                                        const int* __restrict__ in1,
                                        const int* __restrict__ in2,
                                        const int* __restrict__ neg) {
    return (q < BQ) ? in1[q] : (q < 2 * BQ) ? in2[q - BQ] : neg[q - 2 * BQ];
}

// ---------------------------------------------------------------------------
// 1) h1 per slot: tile t == query t (its 16 neighbor slots).
//    256 threads = 4 groups x 64 cols; each group handles 4 slots.
//    W1 staged coalesced ONCE per block (persistent grid-stride over tiles).
// ---------------------------------------------------------------------------
__global__ __launch_bounds__(256) void k_h1(const float* __restrict__ feat,
                                            const int*   __restrict__ adj,
                                            const int*   __restrict__ in1,
                                            const int*   __restrict__ in2,
                                            const int*   __restrict__ neg,
                                            const float* __restrict__ W1,
                                            const float* __restrict__ b1) {
    __shared__ float W1s[D][WPAD];      // natural layout: row j = W1 output row j
    __shared__ float b1s[D];
    __shared__ float xq[4][2 * D][4];   // [group][input dim][slot-sub]

    int tid = threadIdx.x;
    #pragma unroll
    for (int r = 0; r < 32; ++r) {      // fully coalesced: 8192 consecutive floats
        int idx = r * 256 + tid;
        W1s[idx >> 7][idx & 127] = W1[idx];
    }
    if (tid < D) b1s[tid] = b1[tid];

    int g = tid >> 6;   // group 0..3
    int j = tid & 63;   // column 0..63

    for (int t = blockIdx.x; t < NQ; t += GRID_H1) {
        int qn = qnode_of(t, in1, in2, neg);
        #pragma unroll
        for (int s = 0; s < 4; ++s) {
            int kidx = g * 4 + s;
            int node = __ldg(adj + qn * DEG + kidx);
            float self = feat[node * D + j];
            const int* a = adj + node * DEG;
            float s0 = 0.f, s1 = 0.f, s2 = 0.f, s3 = 0.f;
            #pragma unroll
            for (int k = 0; k < DEG; k += 4) {
                s0 += feat[__ldg(a + k    ) * D + j];
                s1 += feat[__ldg(a + k + 1) * D + j];
                s2 += feat[__ldg(a + k + 2) * D + j];
                s3 += feat[__ldg(a + k + 3) * D + j];
            }
            xq[g][j][s]     = self;
            xq[g][D + j][s] = (s0 + s1) + (s2 + s3);
        }
        __syncthreads();   // also covers W1s/b1s on first iteration

        float a0 = b1s[j], a1 = a0, a2 = a0, a3 = a0;
        #pragma unroll 8
        for (int i4 = 0; i4 < (2 * D) / 4; ++i4) {
            float4 w = *(const float4*)&W1s[j][i4 * 4];   // conflict-free row read
            #pragma unroll
            for (int e = 0; e < 4; ++e) {
                float we = (e == 0) ? w.x : (e == 1) ? w.y : (e == 2) ? w.z : w.w;
                float4 xv = *(const float4*)&xq[g][i4 * 4 + e][0];  // warp broadcast
                a0 += we * xv.x; a1 += we * xv.y;
                a2 += we * xv.z; a3 += we * xv.w;
            }
        }

        float* dst = d_h1s + (t * DEG + g * 4) * D + j;   // coalesced 256B per slot
        dst[0 * D] = tanhf(a0);
        dst[1 * D] = tanhf(a1);
        dst[2 * D] = tanhf(a2);
        dst[3 * D] = tanhf(a3);
        __syncthreads();   // xq reused next tile
    }
}

// ---------------------------------------------------------------------------
// 2) hop-2 + normalize: 8 queries / block, 256 threads (2 halves x 128 cols).
//    Neighbor h1 sums are CONTIGUOUS slot rows -> perfectly coalesced streaming.
// ---------------------------------------------------------------------------
__global__ __launch_bounds__(256) void k_hop2(const float* __restrict__ feat,
                                              const int*   __restrict__ in1,
                                              const int*   __restrict__ in2,
                                              const int*   __restrict__ neg,
                                              const float* __restrict__ W2,
                                              const float* __restrict__ b2,
                                              float*       __restrict__ out) {
    __shared__ float x[2 * D][8];       // concat input, query-minor (4 KB)
    __shared__ float ys[8][D2 + 4];
    __shared__ float inv8[8];

    int tid  = threadIdx.x;
    int qb   = blockIdx.x * 8;
    int half = tid >> 7;                // 0 -> queries 0..3, 1 -> queries 4..7
    int col  = tid & 127;

    // gather: each pass covers 4 queries x 64 cols with all 256 threads
    {
        int qs = tid >> 6;              // 0..3
        int j  = tid & 63;
        #pragma unroll
        for (int p = 0; p < 2; ++p) {
            int sq = p * 4 + qs;        // query sub-index 0..7
            int q  = qb + sq;
            float self = 0.f, sum = 0.f;
            if (q < NQ) {
                int node = qnode_of(q, in1, in2, neg);
                self = feat[node * D + j];
                const float* h = d_h1s + (q * DEG) * D + j;   // 16 contiguous rows
                #pragma unroll
                for (int k = 0; k < DEG; ++k)
                    sum += h[k * D];
            }
            x[j][sq]     = self;
            x[D + j][sq] = sum;
        }
    }
    __syncthreads();

    float acc0, acc1, acc2, acc3;
    acc0 = acc1 = acc2 = acc3 = b2[col];
    const float4* wrow = (const float4*)(W2 + col * (2 * D));
    int qoff = half * 4;
    #pragma unroll 8
    for (int i4 = 0; i4 < (2 * D) / 4; ++i4) {
        float4 w = wrow[i4];
        #pragma unroll
        for (int e = 0; e < 4; ++e) {
            float we = (e == 0) ? w.x : (e == 1) ? w.y : (e == 2) ? w.z : w.w;
            float4 xv = *(const float4*)&x[i4 * 4 + e][qoff];   // warp broadcast
            acc0 += we * xv.x; acc1 += we * xv.y;
            acc2 += we * xv.z; acc3 += we * xv.w;
        }
    }

    ys[qoff + 0][col] = acc0;
    ys[qoff + 1][col] = acc1;
    ys[qoff + 2][col] = acc2;
    ys[qoff + 3][col] = acc3;
    __syncthreads();

    {   // warp w reduces query w's squared norm
        int w = tid >> 5, l = tid & 31;
        float v = ys[w][l]      * ys[w][l]
                + ys[w][l + 32] * ys[w][l + 32]
                + ys[w][l + 64] * ys[w][l + 64]
                + ys[w][l + 96] * ys[w][l + 96];
        #pragma unroll
        for (int off = 16; off; off >>= 1)
            v += __shfl_xor_sync(0xffffffffu, v, off);
        if (l == 0) inv8[w] = 1.0f / fmaxf(sqrtf(v), 1e-12f);
    }
    __syncthreads();

    if (qb + qoff + 0 < NQ) out[(qb + qoff + 0) * D2 + col] = acc0 * inv8[qoff + 0];
    if (qb + qoff + 1 < NQ) out[(qb + qoff + 1) * D2 + col] = acc1 * inv8[qoff + 1];
    if (qb + qoff + 2 < NQ) out[(qb + qoff + 2) * D2 + col] = acc2 * inv8[qoff + 2];
    if (qb + qoff + 3 < NQ) out[(qb + qoff + 3) * D2 + col] = acc3 * inv8[qoff + 3];
}

// ---------------------------------------------------------------------------
extern "C" void kernel_launch(void* const* d_in, const int* in_sizes, int n_in,
                              void* d_out, int out_size) {
    const float* feat = (const float*)d_in[0];   // [N, 64]
    const int*   adj  = (const int*)  d_in[1];   // [N, 16]
    const int*   in1  = (const int*)  d_in[2];   // [1024]
    const int*   in2  = (const int*)  d_in[3];   // [1024]
    const int*   neg  = (const int*)  d_in[4];   // [10]
    const float* W1   = (const float*)d_in[5];   // [64, 128]
    const float* b1   = (const float*)d_in[6];   // [64]
    const float* W2   = (const float*)d_in[7];   // [128, 128]
    const float* b2   = (const float*)d_in[8];   // [128]
    float*       out  = (float*)d_out;           // [2058, 128]

    k_h1<<<GRID_H1, 256>>>(feat, adj, in1, in2, neg, W1, b1);
    k_hop2<<<(NQ + 7) / 8, 256>>>(feat, in1, in2, neg, W2, b2, out);
}